// round 13
// baseline (speedup 1.0000x reference)
#include <cuda_runtime.h>
#include <cstdint>
#include <cstddef>

#define B_  2
#define S_  8192
#define D_  1024
#define H_  16
#define HD_ 64
#define A_  1024
#define SQ_ (S_ - A_)   // 7168

// Scratch (allocation-free rule: __device__ globals)
__device__ float g_Q[(size_t)B_ * H_ * S_ * HD_];   // [b,h,s,d]  64 MB
__device__ float g_K[(size_t)B_ * H_ * A_ * HD_];   // [b,h,a,d]   8 MB
__device__ float g_V[(size_t)B_ * H_ * A_ * HD_];   //             8 MB
__device__ float g_AO[(size_t)B_ * S_ * D_];        // [b,s,h*hd+d] 64 MB

// ---------------------------------------------------------------------------
// Tiled SGEMM: 128x128 block tile, K-tile 16, 256 threads, 8x8 per-thread.
// MODE 0: anchors @ Wqkv (+bqkv) -> scatter into g_Q (anchor rows) / g_K / g_V
// MODE 1: queries @ Wq   (+bq)   -> scatter into g_Q (query rows)
// MODE 2: g_AO @ Wproj   (+bproj)-> d_out
// ---------------------------------------------------------------------------
template <int MODE>
__global__ __launch_bounds__(256, 2) void gemm_kernel(
    const float* __restrict__ Ain, const float* __restrict__ Bw,
    const float* __restrict__ bias, float* __restrict__ Cout)
{
    constexpr int NN = (MODE == 0) ? 3 * D_ : D_;

    __shared__ float As[16][132];   // transposed A tile, padded
    __shared__ float Bs[16][128];

    const int tid = threadIdx.x;
    const int tx = tid & 15;
    const int ty = tid >> 4;
    const int rm0 = blockIdx.y * 128;
    const int cn0 = blockIdx.x * 128;

    // A-tile load mapping: m = tid/4 (+64), k0 = (tid%4)*4
    const int a_m = tid >> 2;
    const int a_k = (tid & 3) << 2;

    auto arowptr = [&](int m) -> const float* {
        int r = rm0 + m;
        if constexpr (MODE == 0) {
            int b = r >> 10, s = r & (A_ - 1);
            return Ain + (size_t)(b * S_ + s) * D_;
        } else if constexpr (MODE == 1) {
            int b = r / SQ_, s = r - b * SQ_;
            return Ain + (size_t)(b * S_ + A_ + s) * D_;
        } else {
            return g_AO + (size_t)r * D_;
        }
    };
    const float* arow0 = arowptr(a_m);
    const float* arow1 = arowptr(a_m + 64);

    // B-tile load mapping: k = tid/32 (+8), col = (tid%32)*4
    const int b_k = tid >> 5;
    const int b_c = (tid & 31) << 2;
    const float* bptr = Bw + (size_t)b_k * NN + cn0 + b_c;

    float acc[8][8];
#pragma unroll
    for (int i = 0; i < 8; i++)
#pragma unroll
        for (int j = 0; j < 8; j++) acc[i][j] = 0.f;

#pragma unroll 1
    for (int kt = 0; kt < D_ / 16; ++kt) {
        const int kg = kt << 4;
        float4 av0 = *(const float4*)(arow0 + kg + a_k);
        float4 av1 = *(const float4*)(arow1 + kg + a_k);
        float4 bv0 = *(const float4*)(bptr + (size_t)kg * NN);
        float4 bv1 = *(const float4*)(bptr + (size_t)(kg + 8) * NN);

        __syncthreads();
        As[a_k + 0][a_m] = av0.x; As[a_k + 1][a_m] = av0.y;
        As[a_k + 2][a_m] = av0.z; As[a_k + 3][a_m] = av0.w;
        As[a_k + 0][a_m + 64] = av1.x; As[a_k + 1][a_m + 64] = av1.y;
        As[a_k + 2][a_m + 64] = av1.z; As[a_k + 3][a_m + 64] = av1.w;
        *(float4*)&Bs[b_k][b_c]     = bv0;
        *(float4*)&Bs[b_k + 8][b_c] = bv1;
        __syncthreads();

#pragma unroll
        for (int kk = 0; kk < 16; ++kk) {
            float4 af0 = *(const float4*)&As[kk][ty << 3];
            float4 af1 = *(const float4*)&As[kk][(ty << 3) + 4];
            float4 bf0 = *(const float4*)&Bs[kk][tx << 3];
            float4 bf1 = *(const float4*)&Bs[kk][(tx << 3) + 4];
            float a_[8] = {af0.x, af0.y, af0.z, af0.w, af1.x, af1.y, af1.z, af1.w};
            float b_[8] = {bf0.x, bf0.y, bf0.z, bf0.w, bf1.x, bf1.y, bf1.z, bf1.w};
#pragma unroll
            for (int i = 0; i < 8; i++)
#pragma unroll
                for (int j = 0; j < 8; j++) acc[i][j] += a_[i] * b_[j];
        }
    }

    // Epilogue with bias + scatter
    const int ccol = cn0 + (tx << 3);
    float bia[8];
#pragma unroll
    for (int j = 0; j < 8; j++) bia[j] = bias[ccol + j];

#pragma unroll
    for (int i = 0; i < 8; i++) {
        int r = rm0 + (ty << 3) + i;
        float v[8];
#pragma unroll
        for (int j = 0; j < 8; j++) v[j] = acc[i][j] + bia[j];

        float* dst;
        if constexpr (MODE == 0) {
            int b = r >> 10, s = r & (A_ - 1);
            int three = ccol >> 10;
            int rem = ccol & 1023;
            int h = rem >> 6, d = rem & 63;
            if (three == 0)
                dst = g_Q + ((size_t)(b * H_ + h) * S_ + s) * HD_ + d;
            else if (three == 1)
                dst = g_K + ((size_t)(b * H_ + h) * A_ + s) * HD_ + d;
            else
                dst = g_V + ((size_t)(b * H_ + h) * A_ + s) * HD_ + d;
        } else if constexpr (MODE == 1) {
            int b = r / SQ_, s = r - b * SQ_;
            int h = ccol >> 6, d = ccol & 63;
            dst = g_Q + ((size_t)(b * H_ + h) * S_ + (A_ + s)) * HD_ + d;
        } else {
            dst = Cout + (size_t)r * D_ + ccol;
        }
        *(float4*)(dst)     = make_float4(v[0], v[1], v[2], v[3]);
        *(float4*)(dst + 4) = make_float4(v[4], v[5], v[6], v[7]);
    }
}

// ---------------------------------------------------------------------------
// Flash attention v2: register-blocked like the SGEMM.
// 128 queries/block, 256 threads (16x16), key tiles of 64.
// Thread (ty,tx): S-tile rows q=ty*8+i (i<8), cols k=tx*4+j (j<4);
//                 O-tile rows q=ty*8+i,        cols d=tx*4+j.
// m/l state register-replicated across the 16-lane row group (shfl_xor).
// Dynamic smem (101 KB): Qst[d][q] (transposed, pre-scaled), Kst[d][k]
// (transposed), Vs[k][d], Pst[q][k].
// ---------------------------------------------------------------------------
#define QST_STRIDE 132
#define KST_STRIDE 68
#define ATTN_SMEM_FLOATS (64 * QST_STRIDE + 64 * KST_STRIDE + 64 * KST_STRIDE + 128 * KST_STRIDE)
#define ATTN_SMEM_BYTES  (ATTN_SMEM_FLOATS * 4)

__global__ __launch_bounds__(256, 2) void attn_kernel()
{
    extern __shared__ float sm[];
    float* Qst = sm;                                 // [64][132]  (d, q)
    float* Kst = Qst + 64 * QST_STRIDE;              // [64][68]   (d, k)
    float* Vs  = Kst + 64 * KST_STRIDE;              // [64][68]   (k, d)
    float* Pst = Vs  + 64 * KST_STRIDE;              // [128][68]  (q, k)

    const int tid = threadIdx.x;
    const int tx = tid & 15;
    const int ty = tid >> 4;
    const int b = blockIdx.z, h = blockIdx.y;
    const int bh = b * H_ + h;
    const int q0 = blockIdx.x * 128;

    const float* Qg = g_Q + ((size_t)bh * S_ + q0) * HD_;
    const float* Kb = g_K + (size_t)bh * A_ * HD_;
    const float* Vb = g_V + (size_t)bh * A_ * HD_;

    // Load Q tile transposed into smem, pre-scaled by 1/sqrt(hd)
#pragma unroll
    for (int j = 0; j < 8; ++j) {
        int idx = j * 256 + tid;          // 0..2047 float4s
        int row = idx >> 4;               // q 0..127
        int dg  = idx & 15;               // d group
        float4 v = ((const float4*)(Qg + (size_t)row * HD_))[dg];
        Qst[(4 * dg + 0) * QST_STRIDE + row] = v.x * 0.125f;
        Qst[(4 * dg + 1) * QST_STRIDE + row] = v.y * 0.125f;
        Qst[(4 * dg + 2) * QST_STRIDE + row] = v.z * 0.125f;
        Qst[(4 * dg + 3) * QST_STRIDE + row] = v.w * 0.125f;
    }

    float acc[8][4];
#pragma unroll
    for (int i = 0; i < 8; i++)
#pragma unroll
        for (int j = 0; j < 4; j++) acc[i][j] = 0.f;
    float mrow[8], lrow[8];
#pragma unroll
    for (int i = 0; i < 8; i++) { mrow[i] = -1e30f; lrow[i] = 0.f; }

#pragma unroll 1
    for (int kt = 0; kt < A_ / 64; ++kt) {
        const float* Kt = Kb + (size_t)kt * 64 * HD_;
        const float* Vt = Vb + (size_t)kt * 64 * HD_;

        __syncthreads();   // previous tile's Kst/Vs/Pst reads done
#pragma unroll
        for (int j = 0; j < 4; ++j) {
            int idx = j * 256 + tid;      // 0..1023 float4s
            int row = idx >> 4;           // k 0..63
            int dg  = idx & 15;
            float4 kv = ((const float4*)(Kt + (size_t)row * HD_))[dg];
            Kst[(4 * dg + 0) * KST_STRIDE + row] = kv.x;
            Kst[(4 * dg + 1) * KST_STRIDE + row] = kv.y;
            Kst[(4 * dg + 2) * KST_STRIDE + row] = kv.z;
            Kst[(4 * dg + 3) * KST_STRIDE + row] = kv.w;
            float4 vv = ((const float4*)(Vt + (size_t)row * HD_))[dg];
            *(float4*)&Vs[row * KST_STRIDE + 4 * dg] = vv;
        }
        __syncthreads();

        // S = (Q*scale) . K^T  : 8x4 per thread, k-dim = hd = 64
        float s[8][4];
#pragma unroll
        for (int i = 0; i < 8; i++)
#pragma unroll
            for (int j = 0; j < 4; j++) s[i][j] = 0.f;

#pragma unroll
        for (int d = 0; d < 64; ++d) {
            float4 a0 = *(const float4*)&Qst[d * QST_STRIDE + (ty << 3)];
            float4 a1 = *(const float4*)&Qst[d * QST_STRIDE + (ty << 3) + 4];
            float4 bv = *(const float4*)&Kst[d * KST_STRIDE + (tx << 2)];
            float a_[8] = {a0.x, a0.y, a0.z, a0.w, a1.x, a1.y, a1.z, a1.w};
            float b_[4] = {bv.x, bv.y, bv.z, bv.w};
#pragma unroll
            for (int i = 0; i < 8; i++)
#pragma unroll
                for (int j = 0; j < 4; j++) s[i][j] += a_[i] * b_[j];
        }

        // Online softmax per row; reduce across the 16-lane row group.
#pragma unroll
        for (int i = 0; i < 8; ++i) {
            float tm = fmaxf(fmaxf(s[i][0], s[i][1]), fmaxf(s[i][2], s[i][3]));
            tm = fmaxf(tm, __shfl_xor_sync(0xffffffffu, tm, 1));
            tm = fmaxf(tm, __shfl_xor_sync(0xffffffffu, tm, 2));
            tm = fmaxf(tm, __shfl_xor_sync(0xffffffffu, tm, 4));
            tm = fmaxf(tm, __shfl_xor_sync(0xffffffffu, tm, 8));
            float mn = fmaxf(mrow[i], tm);
            float corr = __expf(mrow[i] - mn);
            mrow[i] = mn;
            float ls = 0.f;
#pragma unroll
            for (int j = 0; j < 4; ++j) {
                float p = __expf(s[i][j] - mn);
                s[i][j] = p;
                ls += p;
            }
            ls += __shfl_xor_sync(0xffffffffu, ls, 1);
            ls += __shfl_xor_sync(0xffffffffu, ls, 2);
            ls += __shfl_xor_sync(0xffffffffu, ls, 4);
            ls += __shfl_xor_sync(0xffffffffu, ls, 8);
            lrow[i] = lrow[i] * corr + ls;
#pragma unroll
            for (int j = 0; j < 4; ++j) acc[i][j] *= corr;
        }

        // P to smem (rows = this thread's q rows, cols = its k cols)
#pragma unroll
        for (int i = 0; i < 8; ++i)
            *(float4*)&Pst[((ty << 3) + i) * KST_STRIDE + (tx << 2)] =
                make_float4(s[i][0], s[i][1], s[i][2], s[i][3]);
        __syncthreads();

        // O += P . V : 8x4 per thread, k-dim = 64, unrolled by 4
#pragma unroll
        for (int k4 = 0; k4 < 16; ++k4) {
            float4 v0 = *(const float4*)&Vs[(k4 * 4 + 0) * KST_STRIDE + (tx << 2)];
            float4 v1 = *(const float4*)&Vs[(k4 * 4 + 1) * KST_STRIDE + (tx << 2)];
            float4 v2 = *(const float4*)&Vs[(k4 * 4 + 2) * KST_STRIDE + (tx << 2)];
            float4 v3 = *(const float4*)&Vs[(k4 * 4 + 3) * KST_STRIDE + (tx << 2)];
#pragma unroll
            for (int i = 0; i < 8; ++i) {
                float4 pv = *(const float4*)&Pst[((ty << 3) + i) * KST_STRIDE + k4 * 4];
                acc[i][0] += pv.x * v0.x + pv.y * v1.x + pv.z * v2.x + pv.w * v3.x;
                acc[i][1] += pv.x * v0.y + pv.y * v1.y + pv.z * v2.y + pv.w * v3.y;
                acc[i][2] += pv.x * v0.z + pv.y * v1.z + pv.z * v2.z + pv.w * v3.z;
                acc[i][3] += pv.x * v0.w + pv.y * v1.w + pv.z * v2.w + pv.w * v3.w;
            }
        }
    }

    // Epilogue: normalize and write [b, s, h*64 + d]
#pragma unroll
    for (int i = 0; i < 8; ++i) {
        float inv = 1.f / lrow[i];
        float* dst = g_AO + (size_t)(b * S_ + q0 + (ty << 3) + i) * D_
                   + h * HD_ + (tx << 2);
        *(float4*)dst = make_float4(acc[i][0] * inv, acc[i][1] * inv,
                                    acc[i][2] * inv, acc[i][3] * inv);
    }
}

// ---------------------------------------------------------------------------
extern "C" void kernel_launch(void* const* d_in, const int* in_sizes, int n_in,
                              void* d_out, int out_size)
{
    const float* x     = (const float*)d_in[0];
    const float* Wqkv  = (const float*)d_in[1];
    const float* bqkv  = (const float*)d_in[2];
    const float* Wq    = (const float*)d_in[3];
    const float* bq    = (const float*)d_in[4];
    const float* Wproj = (const float*)d_in[5];
    const float* bproj = (const float*)d_in[6];
    float* out = (float*)d_out;

    cudaFuncSetAttribute(attn_kernel,
                         cudaFuncAttributeMaxDynamicSharedMemorySize,
                         ATTN_SMEM_BYTES);

    dim3 blk(256);
    // anchors @ Wqkv : M = B*A = 2048, N = 3072
    gemm_kernel<0><<<dim3(3 * D_ / 128, (B_ * A_) / 128), blk>>>(x, Wqkv, bqkv, nullptr);
    // queries @ Wq : M = B*SQ = 14336, N = 1024
    gemm_kernel<1><<<dim3(D_ / 128, (B_ * SQ_) / 128), blk>>>(x, Wq, bq, nullptr);
    // attention: grid (S/128, H, B) = (64, 16, 2)
    attn_kernel<<<dim3(S_ / 128, H_, B_), blk, ATTN_SMEM_BYTES>>>();
    // g_AO @ Wproj : M = B*S = 16384, N = 1024
    gemm_kernel<2><<<dim3(D_ / 128, (B_ * S_) / 128), blk>>>(x, Wproj, bproj, out);
}

// round 14
// speedup vs baseline: 1.0644x; 1.0644x over previous
#include <cuda_runtime.h>
#include <cstdint>
#include <cstddef>

#define B_  2
#define S_  8192
#define D_  1024
#define H_  16
#define HD_ 64
#define A_  1024
#define SQ_ (S_ - A_)   // 7168

// Scratch (allocation-free rule: __device__ globals)
__device__ float g_Q[(size_t)B_ * H_ * S_ * HD_];   // [b,h,s,d]  64 MB
__device__ float g_K[(size_t)B_ * H_ * A_ * HD_];   // [b,h,a,d]   8 MB
__device__ float g_V[(size_t)B_ * H_ * A_ * HD_];   //             8 MB
__device__ float g_AO[(size_t)B_ * S_ * D_];        // [b,s,h*hd+d] 64 MB

// ---------------------------------------------------------------------------
// Packed f32x2 helpers (Blackwell sm_103a): FFMA2 reachable only via PTX.
// ---------------------------------------------------------------------------
typedef unsigned long long u64t;

__device__ __forceinline__ u64t pk2(float lo, float hi) {
    u64t r;
    asm("mov.b64 %0, {%1, %2};" : "=l"(r)
        : "r"(__float_as_uint(lo)), "r"(__float_as_uint(hi)));
    return r;
}
__device__ __forceinline__ u64t pk2dup(float v) {
    u64t r;
    asm("mov.b64 %0, {%1, %1};" : "=l"(r) : "r"(__float_as_uint(v)));
    return r;
}
__device__ __forceinline__ void upk2(u64t v, float& lo, float& hi) {
    unsigned int a, b;
    asm("mov.b64 {%0, %1}, %2;" : "=r"(a), "=r"(b) : "l"(v));
    lo = __uint_as_float(a); hi = __uint_as_float(b);
}
__device__ __forceinline__ void ffma2(u64t& d, u64t a, u64t b) {
    asm("fma.rn.f32x2 %0, %1, %2, %0;" : "+l"(d) : "l"(a), "l"(b));
}
__device__ __forceinline__ void fmul2(u64t& d, u64t a) {
    asm("mul.rn.f32x2 %0, %0, %1;" : "+l"(d) : "l"(a));
}

// ---------------------------------------------------------------------------
// Tiled SGEMM: 128x128 block tile, K-tile 16, 256 threads, 8x8 per-thread,
// inner product via packed FFMA2 (f32x2).
// MODE 0: anchors @ Wqkv (+bqkv) -> scatter into g_Q (anchor rows) / g_K / g_V
// MODE 1: queries @ Wq   (+bq)   -> scatter into g_Q (query rows)
// MODE 2: g_AO @ Wproj   (+bproj)-> d_out
// ---------------------------------------------------------------------------
template <int MODE>
__global__ __launch_bounds__(256, 2) void gemm_kernel(
    const float* __restrict__ Ain, const float* __restrict__ Bw,
    const float* __restrict__ bias, float* __restrict__ Cout)
{
    constexpr int NN = (MODE == 0) ? 3 * D_ : D_;

    __shared__ float As[16][132];   // transposed A tile, padded
    __shared__ float Bs[16][128];

    const int tid = threadIdx.x;
    const int tx = tid & 15;
    const int ty = tid >> 4;
    const int rm0 = blockIdx.y * 128;
    const int cn0 = blockIdx.x * 128;

    // A-tile load mapping: m = tid/4 (+64), k0 = (tid%4)*4
    const int a_m = tid >> 2;
    const int a_k = (tid & 3) << 2;

    auto arowptr = [&](int m) -> const float* {
        int r = rm0 + m;
        if constexpr (MODE == 0) {
            int b = r >> 10, s = r & (A_ - 1);
            return Ain + (size_t)(b * S_ + s) * D_;
        } else if constexpr (MODE == 1) {
            int b = r / SQ_, s = r - b * SQ_;
            return Ain + (size_t)(b * S_ + A_ + s) * D_;
        } else {
            return g_AO + (size_t)r * D_;
        }
    };
    const float* arow0 = arowptr(a_m);
    const float* arow1 = arowptr(a_m + 64);

    // B-tile load mapping: k = tid/32 (+8), col = (tid%32)*4
    const int b_k = tid >> 5;
    const int b_c = (tid & 31) << 2;
    const float* bptr = Bw + (size_t)b_k * NN + cn0 + b_c;

    u64t acc2[8][4];
#pragma unroll
    for (int i = 0; i < 8; i++)
#pragma unroll
        for (int j = 0; j < 4; j++) acc2[i][j] = 0ull;

#pragma unroll 1
    for (int kt = 0; kt < D_ / 16; ++kt) {
        const int kg = kt << 4;
        float4 av0 = *(const float4*)(arow0 + kg + a_k);
        float4 av1 = *(const float4*)(arow1 + kg + a_k);
        float4 bv0 = *(const float4*)(bptr + (size_t)kg * NN);
        float4 bv1 = *(const float4*)(bptr + (size_t)(kg + 8) * NN);

        __syncthreads();
        As[a_k + 0][a_m] = av0.x; As[a_k + 1][a_m] = av0.y;
        As[a_k + 2][a_m] = av0.z; As[a_k + 3][a_m] = av0.w;
        As[a_k + 0][a_m + 64] = av1.x; As[a_k + 1][a_m + 64] = av1.y;
        As[a_k + 2][a_m + 64] = av1.z; As[a_k + 3][a_m + 64] = av1.w;
        *(float4*)&Bs[b_k][b_c]     = bv0;
        *(float4*)&Bs[b_k + 8][b_c] = bv1;
        __syncthreads();

#pragma unroll
        for (int kk = 0; kk < 16; ++kk) {
            float4 af0 = *(const float4*)&As[kk][ty << 3];
            float4 af1 = *(const float4*)&As[kk][(ty << 3) + 4];
            float4 bf0 = *(const float4*)&Bs[kk][tx << 3];
            float4 bf1 = *(const float4*)&Bs[kk][(tx << 3) + 4];
            u64t bp[4] = {pk2(bf0.x, bf0.y), pk2(bf0.z, bf0.w),
                          pk2(bf1.x, bf1.y), pk2(bf1.z, bf1.w)};
            float a_[8] = {af0.x, af0.y, af0.z, af0.w, af1.x, af1.y, af1.z, af1.w};
#pragma unroll
            for (int i = 0; i < 8; i++) {
                u64t ad = pk2dup(a_[i]);
#pragma unroll
                for (int j = 0; j < 4; j++) ffma2(acc2[i][j], ad, bp[j]);
            }
        }
    }

    // Epilogue with bias + scatter
    const int ccol = cn0 + (tx << 3);
    float bia[8];
#pragma unroll
    for (int j = 0; j < 8; j++) bia[j] = bias[ccol + j];

#pragma unroll
    for (int i = 0; i < 8; i++) {
        int r = rm0 + (ty << 3) + i;
        float v[8];
#pragma unroll
        for (int j = 0; j < 4; j++) upk2(acc2[i][j], v[2 * j], v[2 * j + 1]);
#pragma unroll
        for (int j = 0; j < 8; j++) v[j] += bia[j];

        float* dst;
        if constexpr (MODE == 0) {
            int b = r >> 10, s = r & (A_ - 1);
            int three = ccol >> 10;
            int rem = ccol & 1023;
            int h = rem >> 6, d = rem & 63;
            if (three == 0)
                dst = g_Q + ((size_t)(b * H_ + h) * S_ + s) * HD_ + d;
            else if (three == 1)
                dst = g_K + ((size_t)(b * H_ + h) * A_ + s) * HD_ + d;
            else
                dst = g_V + ((size_t)(b * H_ + h) * A_ + s) * HD_ + d;
        } else if constexpr (MODE == 1) {
            int b = r / SQ_, s = r - b * SQ_;
            int h = ccol >> 6, d = ccol & 63;
            dst = g_Q + ((size_t)(b * H_ + h) * S_ + (A_ + s)) * HD_ + d;
        } else {
            dst = Cout + (size_t)r * D_ + ccol;
        }
        *(float4*)(dst)     = make_float4(v[0], v[1], v[2], v[3]);
        *(float4*)(dst + 4) = make_float4(v[4], v[5], v[6], v[7]);
    }
}

// ---------------------------------------------------------------------------
// Flash attention: register-blocked, packed FFMA2 inner loops.
// 128 queries/block, 256 threads (16x16), key tiles of 64.
// Thread (ty,tx): S-tile rows q=ty*8+i (i<8), cols k=tx*4+j (j<4);
//                 O-tile rows q=ty*8+i,        cols d=tx*4+j.
// m/l state register-replicated across the 16-lane row group (shfl_xor).
// ---------------------------------------------------------------------------
#define QST_STRIDE 132
#define KST_STRIDE 68
#define ATTN_SMEM_FLOATS (64 * QST_STRIDE + 64 * KST_STRIDE + 64 * KST_STRIDE + 128 * KST_STRIDE)
#define ATTN_SMEM_BYTES  (ATTN_SMEM_FLOATS * 4)

__global__ __launch_bounds__(256, 2) void attn_kernel()
{
    extern __shared__ float sm[];
    float* Qst = sm;                                 // [64][132]  (d, q)
    float* Kst = Qst + 64 * QST_STRIDE;              // [64][68]   (d, k)
    float* Vs  = Kst + 64 * KST_STRIDE;              // [64][68]   (k, d)
    float* Pst = Vs  + 64 * KST_STRIDE;              // [128][68]  (q, k)

    const int tid = threadIdx.x;
    const int tx = tid & 15;
    const int ty = tid >> 4;
    const int b = blockIdx.z, h = blockIdx.y;
    const int bh = b * H_ + h;
    const int q0 = blockIdx.x * 128;

    const float* Qg = g_Q + ((size_t)bh * S_ + q0) * HD_;
    const float* Kb = g_K + (size_t)bh * A_ * HD_;
    const float* Vb = g_V + (size_t)bh * A_ * HD_;

    // Load Q tile transposed into smem, pre-scaled by 1/sqrt(hd)
#pragma unroll
    for (int j = 0; j < 8; ++j) {
        int idx = j * 256 + tid;          // 0..2047 float4s
        int row = idx >> 4;               // q 0..127
        int dg  = idx & 15;               // d group
        float4 v = ((const float4*)(Qg + (size_t)row * HD_))[dg];
        Qst[(4 * dg + 0) * QST_STRIDE + row] = v.x * 0.125f;
        Qst[(4 * dg + 1) * QST_STRIDE + row] = v.y * 0.125f;
        Qst[(4 * dg + 2) * QST_STRIDE + row] = v.z * 0.125f;
        Qst[(4 * dg + 3) * QST_STRIDE + row] = v.w * 0.125f;
    }

    u64t acc2[8][2];
#pragma unroll
    for (int i = 0; i < 8; i++) { acc2[i][0] = 0ull; acc2[i][1] = 0ull; }
    float mrow[8], lrow[8];
#pragma unroll
    for (int i = 0; i < 8; i++) { mrow[i] = -1e30f; lrow[i] = 0.f; }

#pragma unroll 1
    for (int kt = 0; kt < A_ / 64; ++kt) {
        const float* Kt = Kb + (size_t)kt * 64 * HD_;
        const float* Vt = Vb + (size_t)kt * 64 * HD_;

        __syncthreads();   // previous tile's Kst/Vs/Pst reads done
#pragma unroll
        for (int j = 0; j < 4; ++j) {
            int idx = j * 256 + tid;      // 0..1023 float4s
            int row = idx >> 4;           // k 0..63
            int dg  = idx & 15;
            float4 kv = ((const float4*)(Kt + (size_t)row * HD_))[dg];
            Kst[(4 * dg + 0) * KST_STRIDE + row] = kv.x;
            Kst[(4 * dg + 1) * KST_STRIDE + row] = kv.y;
            Kst[(4 * dg + 2) * KST_STRIDE + row] = kv.z;
            Kst[(4 * dg + 3) * KST_STRIDE + row] = kv.w;
            float4 vv = ((const float4*)(Vt + (size_t)row * HD_))[dg];
            *(float4*)&Vs[row * KST_STRIDE + 4 * dg] = vv;
        }
        __syncthreads();

        // S = (Q*scale) . K^T  : 8x4 per thread (packed 8x2), k-dim = hd = 64
        u64t s2[8][2];
#pragma unroll
        for (int i = 0; i < 8; i++) { s2[i][0] = 0ull; s2[i][1] = 0ull; }

#pragma unroll
        for (int d = 0; d < 64; ++d) {
            float4 a0 = *(const float4*)&Qst[d * QST_STRIDE + (ty << 3)];
            float4 a1 = *(const float4*)&Qst[d * QST_STRIDE + (ty << 3) + 4];
            float4 bv = *(const float4*)&Kst[d * KST_STRIDE + (tx << 2)];
            u64t bp0 = pk2(bv.x, bv.y), bp1 = pk2(bv.z, bv.w);
            float a_[8] = {a0.x, a0.y, a0.z, a0.w, a1.x, a1.y, a1.z, a1.w};
#pragma unroll
            for (int i = 0; i < 8; i++) {
                u64t ad = pk2dup(a_[i]);
                ffma2(s2[i][0], ad, bp0);
                ffma2(s2[i][1], ad, bp1);
            }
        }

        float s[8][4];
#pragma unroll
        for (int i = 0; i < 8; i++) {
            upk2(s2[i][0], s[i][0], s[i][1]);
            upk2(s2[i][1], s[i][2], s[i][3]);
        }

        // Online softmax per row; reduce across the 16-lane row group.
#pragma unroll
        for (int i = 0; i < 8; ++i) {
            float tm = fmaxf(fmaxf(s[i][0], s[i][1]), fmaxf(s[i][2], s[i][3]));
            tm = fmaxf(tm, __shfl_xor_sync(0xffffffffu, tm, 1));
            tm = fmaxf(tm, __shfl_xor_sync(0xffffffffu, tm, 2));
            tm = fmaxf(tm, __shfl_xor_sync(0xffffffffu, tm, 4));
            tm = fmaxf(tm, __shfl_xor_sync(0xffffffffu, tm, 8));
            float mn = fmaxf(mrow[i], tm);
            float corr = __expf(mrow[i] - mn);
            mrow[i] = mn;
            float ls = 0.f;
#pragma unroll
            for (int j = 0; j < 4; ++j) {
                float p = __expf(s[i][j] - mn);
                s[i][j] = p;
                ls += p;
            }
            ls += __shfl_xor_sync(0xffffffffu, ls, 1);
            ls += __shfl_xor_sync(0xffffffffu, ls, 2);
            ls += __shfl_xor_sync(0xffffffffu, ls, 4);
            ls += __shfl_xor_sync(0xffffffffu, ls, 8);
            lrow[i] = lrow[i] * corr + ls;
            u64t cp = pk2dup(corr);
            fmul2(acc2[i][0], cp);
            fmul2(acc2[i][1], cp);
        }

        // P to smem (rows = this thread's q rows, cols = its k cols)
#pragma unroll
        for (int i = 0; i < 8; ++i)
            *(float4*)&Pst[((ty << 3) + i) * KST_STRIDE + (tx << 2)] =
                make_float4(s[i][0], s[i][1], s[i][2], s[i][3]);
        __syncthreads();

        // O += P . V : 8x4 per thread (packed 8x2), k-dim = 64, unrolled by 4
#pragma unroll
        for (int k4 = 0; k4 < 16; ++k4) {
            float4 v0 = *(const float4*)&Vs[(k4 * 4 + 0) * KST_STRIDE + (tx << 2)];
            float4 v1 = *(const float4*)&Vs[(k4 * 4 + 1) * KST_STRIDE + (tx << 2)];
            float4 v2 = *(const float4*)&Vs[(k4 * 4 + 2) * KST_STRIDE + (tx << 2)];
            float4 v3 = *(const float4*)&Vs[(k4 * 4 + 3) * KST_STRIDE + (tx << 2)];
            u64t vp00 = pk2(v0.x, v0.y), vp01 = pk2(v0.z, v0.w);
            u64t vp10 = pk2(v1.x, v1.y), vp11 = pk2(v1.z, v1.w);
            u64t vp20 = pk2(v2.x, v2.y), vp21 = pk2(v2.z, v2.w);
            u64t vp30 = pk2(v3.x, v3.y), vp31 = pk2(v3.z, v3.w);
#pragma unroll
            for (int i = 0; i < 8; ++i) {
                float4 pv = *(const float4*)&Pst[((ty << 3) + i) * KST_STRIDE + k4 * 4];
                u64t p0 = pk2dup(pv.x), p1 = pk2dup(pv.y);
                u64t p2 = pk2dup(pv.z), p3 = pk2dup(pv.w);
                ffma2(acc2[i][0], p0, vp00); ffma2(acc2[i][1], p0, vp01);
                ffma2(acc2[i][0], p1, vp10); ffma2(acc2[i][1], p1, vp11);
                ffma2(acc2[i][0], p2, vp20); ffma2(acc2[i][1], p2, vp21);
                ffma2(acc2[i][0], p3, vp30); ffma2(acc2[i][1], p3, vp31);
            }
        }
    }

    // Epilogue: normalize and write [b, s, h*64 + d]
#pragma unroll
    for (int i = 0; i < 8; ++i) {
        float inv = 1.f / lrow[i];
        float o[4];
        upk2(acc2[i][0], o[0], o[1]);
        upk2(acc2[i][1], o[2], o[3]);
        float* dst = g_AO + (size_t)(b * S_ + q0 + (ty << 3) + i) * D_
                   + h * HD_ + (tx << 2);
        *(float4*)dst = make_float4(o[0] * inv, o[1] * inv, o[2] * inv, o[3] * inv);
    }
}

// ---------------------------------------------------------------------------
extern "C" void kernel_launch(void* const* d_in, const int* in_sizes, int n_in,
                              void* d_out, int out_size)
{
    const float* x     = (const float*)d_in[0];
    const float* Wqkv  = (const float*)d_in[1];
    const float* bqkv  = (const float*)d_in[2];
    const float* Wq    = (const float*)d_in[3];
    const float* bq    = (const float*)d_in[4];
    const float* Wproj = (const float*)d_in[5];
    const float* bproj = (const float*)d_in[6];
    float* out = (float*)d_out;

    cudaFuncSetAttribute(attn_kernel,
                         cudaFuncAttributeMaxDynamicSharedMemorySize,
                         ATTN_SMEM_BYTES);

    dim3 blk(256);
    // anchors @ Wqkv : M = B*A = 2048, N = 3072
    gemm_kernel<0><<<dim3(3 * D_ / 128, (B_ * A_) / 128), blk>>>(x, Wqkv, bqkv, nullptr);
    // queries @ Wq : M = B*SQ = 14336, N = 1024
    gemm_kernel<1><<<dim3(D_ / 128, (B_ * SQ_) / 128), blk>>>(x, Wq, bq, nullptr);
    // attention: grid (S/128, H, B) = (64, 16, 2)
    attn_kernel<<<dim3(S_ / 128, H_, B_), blk, ATTN_SMEM_BYTES>>>();
    // g_AO @ Wproj : M = B*S = 16384, N = 1024
    gemm_kernel<2><<<dim3(D_ / 128, (B_ * S_) / 128), blk>>>(x, Wproj, bproj, out);
}

// round 15
// speedup vs baseline: 1.1520x; 1.0823x over previous
#include <cuda_runtime.h>
#include <cstdint>
#include <cstddef>

#define B_  2
#define S_  8192
#define D_  1024
#define H_  16
#define HD_ 64
#define A_  1024
#define SQ_ (S_ - A_)   // 7168

// Scratch (allocation-free rule: __device__ globals)
__device__ float g_Q[(size_t)B_ * H_ * S_ * HD_];   // [b,h,s,d]  64 MB
__device__ float g_K[(size_t)B_ * H_ * A_ * HD_];   // [b,h,a,d]   8 MB
__device__ float g_V[(size_t)B_ * H_ * A_ * HD_];   //             8 MB
__device__ float g_AO[(size_t)B_ * S_ * D_];        // [b,s,h*hd+d] 64 MB

// ---------------------------------------------------------------------------
// Packed f32x2 helpers (attention kernel)
// ---------------------------------------------------------------------------
typedef unsigned long long u64t;

__device__ __forceinline__ u64t pk2(float lo, float hi) {
    u64t r;
    asm("mov.b64 %0, {%1, %2};" : "=l"(r)
        : "r"(__float_as_uint(lo)), "r"(__float_as_uint(hi)));
    return r;
}
__device__ __forceinline__ u64t pk2dup(float v) {
    u64t r;
    asm("mov.b64 %0, {%1, %1};" : "=l"(r) : "r"(__float_as_uint(v)));
    return r;
}
__device__ __forceinline__ void upk2(u64t v, float& lo, float& hi) {
    unsigned int a, b;
    asm("mov.b64 {%0, %1}, %2;" : "=r"(a), "=r"(b) : "l"(v));
    lo = __uint_as_float(a); hi = __uint_as_float(b);
}
__device__ __forceinline__ void ffma2(u64t& d, u64t a, u64t b) {
    asm("fma.rn.f32x2 %0, %1, %2, %0;" : "+l"(d) : "l"(a), "l"(b));
}
__device__ __forceinline__ void fmul2(u64t& d, u64t a) {
    asm("mul.rn.f32x2 %0, %0, %1;" : "+l"(d) : "l"(a));
}

// ---------------------------------------------------------------------------
// TF32 helpers
// ---------------------------------------------------------------------------
__device__ __forceinline__ unsigned int cvt_tf32(float f) {
    unsigned int r;
    asm("cvt.rna.tf32.f32 %0, %1;" : "=r"(r) : "f"(f));
    return r;
}
// split v into hi (tf32) and lo (tf32 of residual); returned as float bit-patterns
__device__ __forceinline__ void tf32_split(float v, float& hi, float& lo) {
    unsigned int h = cvt_tf32(v);
    float hf = __uint_as_float(h);
    unsigned int l = cvt_tf32(v - hf);
    hi = hf; lo = __uint_as_float(l);
}

__device__ __forceinline__ void mma_tf32(float c[4], const unsigned int a[4],
                                         const unsigned int b[2]) {
    asm("mma.sync.aligned.m16n8k8.row.col.f32.tf32.tf32.f32 "
        "{%0,%1,%2,%3}, {%4,%5,%6,%7}, {%8,%9}, {%0,%1,%2,%3};"
        : "+f"(c[0]), "+f"(c[1]), "+f"(c[2]), "+f"(c[3])
        : "r"(a[0]), "r"(a[1]), "r"(a[2]), "r"(a[3]), "r"(b[0]), "r"(b[1]));
}

// ---------------------------------------------------------------------------
// 3xTF32 tensor-core GEMM: 128x128 block tile, K-tile 16, 256 threads (8 warps).
// Warp grid 4(m) x 2(n); warp tile 32x64 = 2 m-tiles(16) x 8 n-tiles(8).
// hi/lo split done once at smem store; mainloop = LDS + HMMA only.
// A smem stride 20, B smem stride 136 -> conflict-free fragment loads.
// MODE 0: anchors @ Wqkv (+bqkv) -> scatter g_Q/g_K/g_V
// MODE 1: queries @ Wq   (+bq)   -> scatter g_Q
// MODE 2: g_AO @ Wproj   (+bproj)-> d_out
// ---------------------------------------------------------------------------
#define ASTR 20
#define BSTR 136

template <int MODE>
__global__ __launch_bounds__(256, 2) void gemm_kernel(
    const float* __restrict__ Ain, const float* __restrict__ Bw,
    const float* __restrict__ bias, float* __restrict__ Cout)
{
    constexpr int NN = (MODE == 0) ? 3 * D_ : D_;

    __shared__ float Ah[128 * ASTR], Al[128 * ASTR];
    __shared__ float Bh[16 * BSTR],  Bl[16 * BSTR];

    const int tid = threadIdx.x;
    const int wid = tid >> 5;
    const int lane = tid & 31;
    const int g = lane >> 2;        // groupID
    const int t = lane & 3;         // threadID_in_group
    const int m0w = (wid & 3) * 32;
    const int n0w = (wid >> 2) * 64;
    const int rm0 = blockIdx.y * 128;
    const int cn0 = blockIdx.x * 128;

    // Global A-load mapping: rows a_m, a_m+64; cols a_k..a_k+3
    const int a_m = tid >> 2;
    const int a_k = (tid & 3) << 2;

    auto arowptr = [&](int m) -> const float* {
        int r = rm0 + m;
        if constexpr (MODE == 0) {
            int b = r >> 10, s = r & (A_ - 1);
            return Ain + (size_t)(b * S_ + s) * D_;
        } else if constexpr (MODE == 1) {
            int b = r / SQ_, s = r - b * SQ_;
            return Ain + (size_t)(b * S_ + A_ + s) * D_;
        } else {
            return g_AO + (size_t)r * D_;
        }
    };
    const float* arow0 = arowptr(a_m);
    const float* arow1 = arowptr(a_m + 64);

    // Global B-load mapping: rows b_k, b_k+8; cols b_c..b_c+3
    const int b_k = tid >> 5;
    const int b_c = (tid & 31) << 2;
    const float* bptr = Bw + (size_t)b_k * NN + cn0 + b_c;

    float acc[2][8][4];
#pragma unroll
    for (int mt = 0; mt < 2; mt++)
#pragma unroll
        for (int nt = 0; nt < 8; nt++)
#pragma unroll
            for (int e = 0; e < 4; e++) acc[mt][nt][e] = 0.f;

#pragma unroll 1
    for (int kt = 0; kt < D_ / 16; ++kt) {
        const int kg = kt << 4;
        float4 av0 = *(const float4*)(arow0 + kg + a_k);
        float4 av1 = *(const float4*)(arow1 + kg + a_k);
        float4 bv0 = *(const float4*)(bptr + (size_t)kg * NN);
        float4 bv1 = *(const float4*)(bptr + (size_t)(kg + 8) * NN);

        __syncthreads();
        // split + store A
        {
            float4 h4, l4;
            tf32_split(av0.x, h4.x, l4.x); tf32_split(av0.y, h4.y, l4.y);
            tf32_split(av0.z, h4.z, l4.z); tf32_split(av0.w, h4.w, l4.w);
            *(float4*)&Ah[a_m * ASTR + a_k] = h4;
            *(float4*)&Al[a_m * ASTR + a_k] = l4;
            tf32_split(av1.x, h4.x, l4.x); tf32_split(av1.y, h4.y, l4.y);
            tf32_split(av1.z, h4.z, l4.z); tf32_split(av1.w, h4.w, l4.w);
            *(float4*)&Ah[(a_m + 64) * ASTR + a_k] = h4;
            *(float4*)&Al[(a_m + 64) * ASTR + a_k] = l4;
        }
        // split + store B
        {
            float4 h4, l4;
            tf32_split(bv0.x, h4.x, l4.x); tf32_split(bv0.y, h4.y, l4.y);
            tf32_split(bv0.z, h4.z, l4.z); tf32_split(bv0.w, h4.w, l4.w);
            *(float4*)&Bh[b_k * BSTR + b_c] = h4;
            *(float4*)&Bl[b_k * BSTR + b_c] = l4;
            tf32_split(bv1.x, h4.x, l4.x); tf32_split(bv1.y, h4.y, l4.y);
            tf32_split(bv1.z, h4.z, l4.z); tf32_split(bv1.w, h4.w, l4.w);
            *(float4*)&Bh[(b_k + 8) * BSTR + b_c] = h4;
            *(float4*)&Bl[(b_k + 8) * BSTR + b_c] = l4;
        }
        __syncthreads();

#pragma unroll
        for (int ks = 0; ks < 16; ks += 8) {
            // A fragments (hi & lo) for 2 m-tiles
            unsigned int ahi[2][4], alo[2][4];
#pragma unroll
            for (int mt = 0; mt < 2; mt++) {
                int mrow = m0w + mt * 16 + g;
                ahi[mt][0] = __float_as_uint(Ah[(mrow)     * ASTR + ks + t]);
                ahi[mt][1] = __float_as_uint(Ah[(mrow + 8) * ASTR + ks + t]);
                ahi[mt][2] = __float_as_uint(Ah[(mrow)     * ASTR + ks + t + 4]);
                ahi[mt][3] = __float_as_uint(Ah[(mrow + 8) * ASTR + ks + t + 4]);
                alo[mt][0] = __float_as_uint(Al[(mrow)     * ASTR + ks + t]);
                alo[mt][1] = __float_as_uint(Al[(mrow + 8) * ASTR + ks + t]);
                alo[mt][2] = __float_as_uint(Al[(mrow)     * ASTR + ks + t + 4]);
                alo[mt][3] = __float_as_uint(Al[(mrow + 8) * ASTR + ks + t + 4]);
            }
#pragma unroll
            for (int nt = 0; nt < 8; nt++) {
                int ncol = n0w + nt * 8 + g;
                unsigned int bhi[2], blo[2];
                bhi[0] = __float_as_uint(Bh[(ks + t)     * BSTR + ncol]);
                bhi[1] = __float_as_uint(Bh[(ks + t + 4) * BSTR + ncol]);
                blo[0] = __float_as_uint(Bl[(ks + t)     * BSTR + ncol]);
                blo[1] = __float_as_uint(Bl[(ks + t + 4) * BSTR + ncol]);
#pragma unroll
                for (int mt = 0; mt < 2; mt++) {
                    mma_tf32(acc[mt][nt], ahi[mt], bhi);
                    mma_tf32(acc[mt][nt], ahi[mt], blo);
                    mma_tf32(acc[mt][nt], alo[mt], bhi);
                }
            }
        }
    }

    // Epilogue: per C fragment, rows g / g+8, cols 2t / 2t+1 (float2 stores)
#pragma unroll
    for (int nt = 0; nt < 8; nt++) {
        int c = cn0 + n0w + nt * 8 + 2 * t;
        float2 bi = *(const float2*)&bias[c];
#pragma unroll
        for (int mt = 0; mt < 2; mt++) {
#pragma unroll
            for (int half = 0; half < 2; half++) {
                int r = rm0 + m0w + mt * 16 + g + half * 8;
                float2 v = make_float2(acc[mt][nt][2 * half] + bi.x,
                                       acc[mt][nt][2 * half + 1] + bi.y);
                float* dst;
                if constexpr (MODE == 0) {
                    int b = r >> 10, s = r & (A_ - 1);
                    int three = c >> 10;
                    int rem = c & 1023;
                    int h = rem >> 6, d = rem & 63;
                    if (three == 0)
                        dst = g_Q + ((size_t)(b * H_ + h) * S_ + s) * HD_ + d;
                    else if (three == 1)
                        dst = g_K + ((size_t)(b * H_ + h) * A_ + s) * HD_ + d;
                    else
                        dst = g_V + ((size_t)(b * H_ + h) * A_ + s) * HD_ + d;
                } else if constexpr (MODE == 1) {
                    int b = r / SQ_, s = r - b * SQ_;
                    int h = c >> 6, d = c & 63;
                    dst = g_Q + ((size_t)(b * H_ + h) * S_ + (A_ + s)) * HD_ + d;
                } else {
                    dst = Cout + (size_t)r * D_ + c;
                }
                *(float2*)dst = v;
            }
        }
    }
}

// ---------------------------------------------------------------------------
// Flash attention: register-blocked, packed FFMA2 inner loops (unchanged).
// ---------------------------------------------------------------------------
#define QST_STRIDE 132
#define KST_STRIDE 68
#define ATTN_SMEM_FLOATS (64 * QST_STRIDE + 64 * KST_STRIDE + 64 * KST_STRIDE + 128 * KST_STRIDE)
#define ATTN_SMEM_BYTES  (ATTN_SMEM_FLOATS * 4)

__global__ __launch_bounds__(256, 2) void attn_kernel()
{
    extern __shared__ float sm[];
    float* Qst = sm;                                 // [64][132]  (d, q)
    float* Kst = Qst + 64 * QST_STRIDE;              // [64][68]   (d, k)
    float* Vs  = Kst + 64 * KST_STRIDE;              // [64][68]   (k, d)
    float* Pst = Vs  + 64 * KST_STRIDE;              // [128][68]  (q, k)

    const int tid = threadIdx.x;
    const int tx = tid & 15;
    const int ty = tid >> 4;
    const int b = blockIdx.z, h = blockIdx.y;
    const int bh = b * H_ + h;
    const int q0 = blockIdx.x * 128;

    const float* Qg = g_Q + ((size_t)bh * S_ + q0) * HD_;
    const float* Kb = g_K + (size_t)bh * A_ * HD_;
    const float* Vb = g_V + (size_t)bh * A_ * HD_;

#pragma unroll
    for (int j = 0; j < 8; ++j) {
        int idx = j * 256 + tid;
        int row = idx >> 4;
        int dg  = idx & 15;
        float4 v = ((const float4*)(Qg + (size_t)row * HD_))[dg];
        Qst[(4 * dg + 0) * QST_STRIDE + row] = v.x * 0.125f;
        Qst[(4 * dg + 1) * QST_STRIDE + row] = v.y * 0.125f;
        Qst[(4 * dg + 2) * QST_STRIDE + row] = v.z * 0.125f;
        Qst[(4 * dg + 3) * QST_STRIDE + row] = v.w * 0.125f;
    }

    u64t acc2[8][2];
#pragma unroll
    for (int i = 0; i < 8; i++) { acc2[i][0] = 0ull; acc2[i][1] = 0ull; }
    float mrow[8], lrow[8];
#pragma unroll
    for (int i = 0; i < 8; i++) { mrow[i] = -1e30f; lrow[i] = 0.f; }

#pragma unroll 1
    for (int kt = 0; kt < A_ / 64; ++kt) {
        const float* Kt = Kb + (size_t)kt * 64 * HD_;
        const float* Vt = Vb + (size_t)kt * 64 * HD_;

        __syncthreads();
#pragma unroll
        for (int j = 0; j < 4; ++j) {
            int idx = j * 256 + tid;
            int row = idx >> 4;
            int dg  = idx & 15;
            float4 kv = ((const float4*)(Kt + (size_t)row * HD_))[dg];
            Kst[(4 * dg + 0) * KST_STRIDE + row] = kv.x;
            Kst[(4 * dg + 1) * KST_STRIDE + row] = kv.y;
            Kst[(4 * dg + 2) * KST_STRIDE + row] = kv.z;
            Kst[(4 * dg + 3) * KST_STRIDE + row] = kv.w;
            float4 vv = ((const float4*)(Vt + (size_t)row * HD_))[dg];
            *(float4*)&Vs[row * KST_STRIDE + 4 * dg] = vv;
        }
        __syncthreads();

        u64t s2[8][2];
#pragma unroll
        for (int i = 0; i < 8; i++) { s2[i][0] = 0ull; s2[i][1] = 0ull; }

#pragma unroll
        for (int d = 0; d < 64; ++d) {
            float4 a0 = *(const float4*)&Qst[d * QST_STRIDE + (ty << 3)];
            float4 a1 = *(const float4*)&Qst[d * QST_STRIDE + (ty << 3) + 4];
            float4 bv = *(const float4*)&Kst[d * KST_STRIDE + (tx << 2)];
            u64t bp0 = pk2(bv.x, bv.y), bp1 = pk2(bv.z, bv.w);
            float a_[8] = {a0.x, a0.y, a0.z, a0.w, a1.x, a1.y, a1.z, a1.w};
#pragma unroll
            for (int i = 0; i < 8; i++) {
                u64t ad = pk2dup(a_[i]);
                ffma2(s2[i][0], ad, bp0);
                ffma2(s2[i][1], ad, bp1);
            }
        }

        float s[8][4];
#pragma unroll
        for (int i = 0; i < 8; i++) {
            upk2(s2[i][0], s[i][0], s[i][1]);
            upk2(s2[i][1], s[i][2], s[i][3]);
        }

#pragma unroll
        for (int i = 0; i < 8; ++i) {
            float tm = fmaxf(fmaxf(s[i][0], s[i][1]), fmaxf(s[i][2], s[i][3]));
            tm = fmaxf(tm, __shfl_xor_sync(0xffffffffu, tm, 1));
            tm = fmaxf(tm, __shfl_xor_sync(0xffffffffu, tm, 2));
            tm = fmaxf(tm, __shfl_xor_sync(0xffffffffu, tm, 4));
            tm = fmaxf(tm, __shfl_xor_sync(0xffffffffu, tm, 8));
            float mn = fmaxf(mrow[i], tm);
            float corr = __expf(mrow[i] - mn);
            mrow[i] = mn;
            float ls = 0.f;
#pragma unroll
            for (int j = 0; j < 4; ++j) {
                float p = __expf(s[i][j] - mn);
                s[i][j] = p;
                ls += p;
            }
            ls += __shfl_xor_sync(0xffffffffu, ls, 1);
            ls += __shfl_xor_sync(0xffffffffu, ls, 2);
            ls += __shfl_xor_sync(0xffffffffu, ls, 4);
            ls += __shfl_xor_sync(0xffffffffu, ls, 8);
            lrow[i] = lrow[i] * corr + ls;
            u64t cp = pk2dup(corr);
            fmul2(acc2[i][0], cp);
            fmul2(acc2[i][1], cp);
        }

#pragma unroll
        for (int i = 0; i < 8; ++i)
            *(float4*)&Pst[((ty << 3) + i) * KST_STRIDE + (tx << 2)] =
                make_float4(s[i][0], s[i][1], s[i][2], s[i][3]);
        __syncthreads();

#pragma unroll
        for (int k4 = 0; k4 < 16; ++k4) {
            float4 v0 = *(const float4*)&Vs[(k4 * 4 + 0) * KST_STRIDE + (tx << 2)];
            float4 v1 = *(const float4*)&Vs[(k4 * 4 + 1) * KST_STRIDE + (tx << 2)];
            float4 v2 = *(const float4*)&Vs[(k4 * 4 + 2) * KST_STRIDE + (tx << 2)];
            float4 v3 = *(const float4*)&Vs[(k4 * 4 + 3) * KST_STRIDE + (tx << 2)];
            u64t vp00 = pk2(v0.x, v0.y), vp01 = pk2(v0.z, v0.w);
            u64t vp10 = pk2(v1.x, v1.y), vp11 = pk2(v1.z, v1.w);
            u64t vp20 = pk2(v2.x, v2.y), vp21 = pk2(v2.z, v2.w);
            u64t vp30 = pk2(v3.x, v3.y), vp31 = pk2(v3.z, v3.w);
#pragma unroll
            for (int i = 0; i < 8; ++i) {
                float4 pv = *(const float4*)&Pst[((ty << 3) + i) * KST_STRIDE + k4 * 4];
                u64t p0 = pk2dup(pv.x), p1 = pk2dup(pv.y);
                u64t p2 = pk2dup(pv.z), p3 = pk2dup(pv.w);
                ffma2(acc2[i][0], p0, vp00); ffma2(acc2[i][1], p0, vp01);
                ffma2(acc2[i][0], p1, vp10); ffma2(acc2[i][1], p1, vp11);
                ffma2(acc2[i][0], p2, vp20); ffma2(acc2[i][1], p2, vp21);
                ffma2(acc2[i][0], p3, vp30); ffma2(acc2[i][1], p3, vp31);
            }
        }
    }

#pragma unroll
    for (int i = 0; i < 8; ++i) {
        float inv = 1.f / lrow[i];
        float o[4];
        upk2(acc2[i][0], o[0], o[1]);
        upk2(acc2[i][1], o[2], o[3]);
        float* dst = g_AO + (size_t)(b * S_ + q0 + (ty << 3) + i) * D_
                   + h * HD_ + (tx << 2);
        *(float4*)dst = make_float4(o[0] * inv, o[1] * inv, o[2] * inv, o[3] * inv);
    }
}

// ---------------------------------------------------------------------------
extern "C" void kernel_launch(void* const* d_in, const int* in_sizes, int n_in,
                              void* d_out, int out_size)
{
    const float* x     = (const float*)d_in[0];
    const float* Wqkv  = (const float*)d_in[1];
    const float* bqkv  = (const float*)d_in[2];
    const float* Wq    = (const float*)d_in[3];
    const float* bq    = (const float*)d_in[4];
    const float* Wproj = (const float*)d_in[5];
    const float* bproj = (const float*)d_in[6];
    float* out = (float*)d_out;

    cudaFuncSetAttribute(attn_kernel,
                         cudaFuncAttributeMaxDynamicSharedMemorySize,
                         ATTN_SMEM_BYTES);

    dim3 blk(256);
    // anchors @ Wqkv : M = B*A = 2048, N = 3072
    gemm_kernel<0><<<dim3(3 * D_ / 128, (B_ * A_) / 128), blk>>>(x, Wqkv, bqkv, nullptr);
    // queries @ Wq : M = B*SQ = 14336, N = 1024
    gemm_kernel<1><<<dim3(D_ / 128, (B_ * SQ_) / 128), blk>>>(x, Wq, bq, nullptr);
    // attention: grid (S/128, H, B) = (64, 16, 2)
    attn_kernel<<<dim3(S_ / 128, H_, B_), blk, ATTN_SMEM_BYTES>>>();
    // g_AO @ Wproj : M = B*S = 16384, N = 1024
    gemm_kernel<2><<<dim3(D_ / 128, (B_ * S_) / 128), blk>>>(x, Wproj, bproj, out);
}

// round 16
// speedup vs baseline: 1.6391x; 1.4229x over previous
#include <cuda_runtime.h>
#include <cstdint>
#include <cstddef>

#define B_  2
#define S_  8192
#define D_  1024
#define H_  16
#define HD_ 64
#define A_  1024
#define SQ_ (S_ - A_)   // 7168

// Scratch (allocation-free rule: __device__ globals)
__device__ float g_Q[(size_t)B_ * H_ * S_ * HD_];   // [b,h,s,d]  64 MB
__device__ float g_K[(size_t)B_ * H_ * A_ * HD_];   // [b,h,a,d]   8 MB
__device__ float g_V[(size_t)B_ * H_ * A_ * HD_];   //             8 MB
__device__ float g_AO[(size_t)B_ * S_ * D_];        // [b,s,h*hd+d] 64 MB

// ---------------------------------------------------------------------------
// TF32 helpers
// ---------------------------------------------------------------------------
__device__ __forceinline__ unsigned int cvt_tf32(float f) {
    unsigned int r;
    asm("cvt.rna.tf32.f32 %0, %1;" : "=r"(r) : "f"(f));
    return r;
}
__device__ __forceinline__ float tf32f(float f) {
    return __uint_as_float(cvt_tf32(f));
}
// split v into hi (tf32) and lo (tf32 of residual); returned as float bit-patterns
__device__ __forceinline__ void tf32_split(float v, float& hi, float& lo) {
    unsigned int h = cvt_tf32(v);
    float hf = __uint_as_float(h);
    unsigned int l = cvt_tf32(v - hf);
    hi = hf; lo = __uint_as_float(l);
}

__device__ __forceinline__ void mma_tf32(float c[4], const unsigned int a[4],
                                         const unsigned int b[2]) {
    asm("mma.sync.aligned.m16n8k8.row.col.f32.tf32.tf32.f32 "
        "{%0,%1,%2,%3}, {%4,%5,%6,%7}, {%8,%9}, {%0,%1,%2,%3};"
        : "+f"(c[0]), "+f"(c[1]), "+f"(c[2]), "+f"(c[3])
        : "r"(a[0]), "r"(a[1]), "r"(a[2]), "r"(a[3]), "r"(b[0]), "r"(b[1]));
}

// ---------------------------------------------------------------------------
// 3xTF32 tensor-core GEMM (unchanged from R15): 128x128 block tile, K-tile 16,
// 256 threads (8 warps), warp tile 32x64.
// MODE 0: anchors @ Wqkv (+bqkv) -> scatter g_Q/g_K/g_V
// MODE 1: queries @ Wq   (+bq)   -> scatter g_Q
// MODE 2: g_AO @ Wproj   (+bproj)-> d_out
// ---------------------------------------------------------------------------
#define ASTR 20
#define BSTR 136

template <int MODE>
__global__ __launch_bounds__(256, 2) void gemm_kernel(
    const float* __restrict__ Ain, const float* __restrict__ Bw,
    const float* __restrict__ bias, float* __restrict__ Cout)
{
    constexpr int NN = (MODE == 0) ? 3 * D_ : D_;

    __shared__ float Ah[128 * ASTR], Al[128 * ASTR];
    __shared__ float Bh[16 * BSTR],  Bl[16 * BSTR];

    const int tid = threadIdx.x;
    const int wid = tid >> 5;
    const int lane = tid & 31;
    const int g = lane >> 2;        // groupID
    const int t = lane & 3;         // threadID_in_group
    const int m0w = (wid & 3) * 32;
    const int n0w = (wid >> 2) * 64;
    const int rm0 = blockIdx.y * 128;
    const int cn0 = blockIdx.x * 128;

    const int a_m = tid >> 2;
    const int a_k = (tid & 3) << 2;

    auto arowptr = [&](int m) -> const float* {
        int r = rm0 + m;
        if constexpr (MODE == 0) {
            int b = r >> 10, s = r & (A_ - 1);
            return Ain + (size_t)(b * S_ + s) * D_;
        } else if constexpr (MODE == 1) {
            int b = r / SQ_, s = r - b * SQ_;
            return Ain + (size_t)(b * S_ + A_ + s) * D_;
        } else {
            return g_AO + (size_t)r * D_;
        }
    };
    const float* arow0 = arowptr(a_m);
    const float* arow1 = arowptr(a_m + 64);

    const int b_k = tid >> 5;
    const int b_c = (tid & 31) << 2;
    const float* bptr = Bw + (size_t)b_k * NN + cn0 + b_c;

    float acc[2][8][4];
#pragma unroll
    for (int mt = 0; mt < 2; mt++)
#pragma unroll
        for (int nt = 0; nt < 8; nt++)
#pragma unroll
            for (int e = 0; e < 4; e++) acc[mt][nt][e] = 0.f;

#pragma unroll 1
    for (int kt = 0; kt < D_ / 16; ++kt) {
        const int kg = kt << 4;
        float4 av0 = *(const float4*)(arow0 + kg + a_k);
        float4 av1 = *(const float4*)(arow1 + kg + a_k);
        float4 bv0 = *(const float4*)(bptr + (size_t)kg * NN);
        float4 bv1 = *(const float4*)(bptr + (size_t)(kg + 8) * NN);

        __syncthreads();
        {
            float4 h4, l4;
            tf32_split(av0.x, h4.x, l4.x); tf32_split(av0.y, h4.y, l4.y);
            tf32_split(av0.z, h4.z, l4.z); tf32_split(av0.w, h4.w, l4.w);
            *(float4*)&Ah[a_m * ASTR + a_k] = h4;
            *(float4*)&Al[a_m * ASTR + a_k] = l4;
            tf32_split(av1.x, h4.x, l4.x); tf32_split(av1.y, h4.y, l4.y);
            tf32_split(av1.z, h4.z, l4.z); tf32_split(av1.w, h4.w, l4.w);
            *(float4*)&Ah[(a_m + 64) * ASTR + a_k] = h4;
            *(float4*)&Al[(a_m + 64) * ASTR + a_k] = l4;
        }
        {
            float4 h4, l4;
            tf32_split(bv0.x, h4.x, l4.x); tf32_split(bv0.y, h4.y, l4.y);
            tf32_split(bv0.z, h4.z, l4.z); tf32_split(bv0.w, h4.w, l4.w);
            *(float4*)&Bh[b_k * BSTR + b_c] = h4;
            *(float4*)&Bl[b_k * BSTR + b_c] = l4;
            tf32_split(bv1.x, h4.x, l4.x); tf32_split(bv1.y, h4.y, l4.y);
            tf32_split(bv1.z, h4.z, l4.z); tf32_split(bv1.w, h4.w, l4.w);
            *(float4*)&Bh[(b_k + 8) * BSTR + b_c] = h4;
            *(float4*)&Bl[(b_k + 8) * BSTR + b_c] = l4;
        }
        __syncthreads();

#pragma unroll
        for (int ks = 0; ks < 16; ks += 8) {
            unsigned int ahi[2][4], alo[2][4];
#pragma unroll
            for (int mt = 0; mt < 2; mt++) {
                int mrow = m0w + mt * 16 + g;
                ahi[mt][0] = __float_as_uint(Ah[(mrow)     * ASTR + ks + t]);
                ahi[mt][1] = __float_as_uint(Ah[(mrow + 8) * ASTR + ks + t]);
                ahi[mt][2] = __float_as_uint(Ah[(mrow)     * ASTR + ks + t + 4]);
                ahi[mt][3] = __float_as_uint(Ah[(mrow + 8) * ASTR + ks + t + 4]);
                alo[mt][0] = __float_as_uint(Al[(mrow)     * ASTR + ks + t]);
                alo[mt][1] = __float_as_uint(Al[(mrow + 8) * ASTR + ks + t]);
                alo[mt][2] = __float_as_uint(Al[(mrow)     * ASTR + ks + t + 4]);
                alo[mt][3] = __float_as_uint(Al[(mrow + 8) * ASTR + ks + t + 4]);
            }
#pragma unroll
            for (int nt = 0; nt < 8; nt++) {
                int ncol = n0w + nt * 8 + g;
                unsigned int bhi[2], blo[2];
                bhi[0] = __float_as_uint(Bh[(ks + t)     * BSTR + ncol]);
                bhi[1] = __float_as_uint(Bh[(ks + t + 4) * BSTR + ncol]);
                blo[0] = __float_as_uint(Bl[(ks + t)     * BSTR + ncol]);
                blo[1] = __float_as_uint(Bl[(ks + t + 4) * BSTR + ncol]);
#pragma unroll
                for (int mt = 0; mt < 2; mt++) {
                    mma_tf32(acc[mt][nt], ahi[mt], bhi);
                    mma_tf32(acc[mt][nt], ahi[mt], blo);
                    mma_tf32(acc[mt][nt], alo[mt], bhi);
                }
            }
        }
    }

#pragma unroll
    for (int nt = 0; nt < 8; nt++) {
        int c = cn0 + n0w + nt * 8 + 2 * t;
        float2 bi = *(const float2*)&bias[c];
#pragma unroll
        for (int mt = 0; mt < 2; mt++) {
#pragma unroll
            for (int half = 0; half < 2; half++) {
                int r = rm0 + m0w + mt * 16 + g + half * 8;
                float2 v = make_float2(acc[mt][nt][2 * half] + bi.x,
                                       acc[mt][nt][2 * half + 1] + bi.y);
                float* dst;
                if constexpr (MODE == 0) {
                    int b = r >> 10, s = r & (A_ - 1);
                    int three = c >> 10;
                    int rem = c & 1023;
                    int h = rem >> 6, d = rem & 63;
                    if (three == 0)
                        dst = g_Q + ((size_t)(b * H_ + h) * S_ + s) * HD_ + d;
                    else if (three == 1)
                        dst = g_K + ((size_t)(b * H_ + h) * A_ + s) * HD_ + d;
                    else
                        dst = g_V + ((size_t)(b * H_ + h) * A_ + s) * HD_ + d;
                } else if constexpr (MODE == 1) {
                    int b = r / SQ_, s = r - b * SQ_;
                    int h = c >> 6, d = c & 63;
                    dst = g_Q + ((size_t)(b * H_ + h) * S_ + (A_ + s)) * HD_ + d;
                } else {
                    dst = Cout + (size_t)r * D_ + c;
                }
                *(float2*)dst = v;
            }
        }
    }
}

// ---------------------------------------------------------------------------
// Flash attention v3: 1x TF32 tensor-core MMA.
// 128 queries/block, 256 threads (8 warps). Warp w owns q-rows 16w..16w+15
// and ALL 64 keys / 64 hd columns -> softmax reductions are intra-warp
// (shfl_xor 1,2 within each 4-lane quad sharing a row).
// Q fragments register-resident (staged once, scaled + tf32).
// K and V stored naturally [key][d] at stride 72 -> all fragment LDS
// patterns (g*8+t or t*8+g mod 32) conflict-free.
// P round-trips through the Q-staging smem rows owned by this warp only
// (-> __syncwarp, no block barrier).
// ---------------------------------------------------------------------------
#define PSTR 72
#define ATTN_SMEM_FLOATS (128 * PSTR + 64 * PSTR + 64 * PSTR)   // 18432
#define ATTN_SMEM_BYTES  (ATTN_SMEM_FLOATS * 4)                 // 72 KB

__global__ __launch_bounds__(256, 2) void attn_kernel()
{
    extern __shared__ float sm[];
    float* QP = sm;                       // [128][72]  Q staging, then P
    float* Ks = QP + 128 * PSTR;          // [64][72]   K tile [key][d]
    float* Vs = Ks + 64 * PSTR;           // [64][72]   V tile [key][d]

    const int tid = threadIdx.x;
    const int wid = tid >> 5;
    const int lane = tid & 31;
    const int g = lane >> 2;
    const int t = lane & 3;
    const int b = blockIdx.z, h = blockIdx.y;
    const int bh = b * H_ + h;
    const int q0 = blockIdx.x * 128;

    const float* Qg = g_Q + ((size_t)bh * S_ + q0) * HD_;
    const float* Kb = g_K + (size_t)bh * A_ * HD_;
    const float* Vb = g_V + (size_t)bh * A_ * HD_;

    // Stage Q tile: scale by 1/sqrt(hd), convert to tf32
#pragma unroll
    for (int j = 0; j < 8; ++j) {
        int idx = j * 256 + tid;          // 0..2047 float4s
        int row = idx >> 4;               // q 0..127
        int dg  = idx & 15;
        float4 v = ((const float4*)(Qg + (size_t)row * HD_))[dg];
        float* p = &QP[row * PSTR + 4 * dg];
        p[0] = tf32f(v.x * 0.125f);
        p[1] = tf32f(v.y * 0.125f);
        p[2] = tf32f(v.z * 0.125f);
        p[3] = tf32f(v.w * 0.125f);
    }
    __syncthreads();

    // Q fragments: warp's 16 rows, hd split into 8 k-steps
    const int mr = wid * 16 + g;
    unsigned int qf[8][4];
#pragma unroll
    for (int ks = 0; ks < 8; ++ks) {
        qf[ks][0] = __float_as_uint(QP[(mr)     * PSTR + 8 * ks + t]);
        qf[ks][1] = __float_as_uint(QP[(mr + 8) * PSTR + 8 * ks + t]);
        qf[ks][2] = __float_as_uint(QP[(mr)     * PSTR + 8 * ks + t + 4]);
        qf[ks][3] = __float_as_uint(QP[(mr + 8) * PSTR + 8 * ks + t + 4]);
    }

    float oa[8][4];
#pragma unroll
    for (int nt = 0; nt < 8; nt++)
#pragma unroll
        for (int e = 0; e < 4; e++) oa[nt][e] = 0.f;
    float m0 = -1e30f, m1 = -1e30f, l0 = 0.f, l1 = 0.f;

#pragma unroll 1
    for (int kt = 0; kt < A_ / 64; ++kt) {
        const float* Kt = Kb + (size_t)kt * 64 * HD_;
        const float* Vt = Vb + (size_t)kt * 64 * HD_;

        __syncthreads();   // prev tile's Ks/Vs reads done
#pragma unroll
        for (int j = 0; j < 4; ++j) {
            int idx = j * 256 + tid;      // 0..1023 float4s
            int key = idx >> 4;
            int dg  = idx & 15;
            float4 kv = ((const float4*)(Kt + (size_t)key * HD_))[dg];
            float* kp = &Ks[key * PSTR + 4 * dg];
            kp[0] = tf32f(kv.x); kp[1] = tf32f(kv.y);
            kp[2] = tf32f(kv.z); kp[3] = tf32f(kv.w);
            float4 vv = ((const float4*)(Vt + (size_t)key * HD_))[dg];
            float* vp = &Vs[key * PSTR + 4 * dg];
            vp[0] = tf32f(vv.x); vp[1] = tf32f(vv.y);
            vp[2] = tf32f(vv.z); vp[3] = tf32f(vv.w);
        }
        __syncthreads();

        // S = Q.K^T : m16 x n64 per warp, contraction over hd=64
        float s[8][4];
#pragma unroll
        for (int nt = 0; nt < 8; nt++)
#pragma unroll
            for (int e = 0; e < 4; e++) s[nt][e] = 0.f;

#pragma unroll
        for (int ks = 0; ks < 8; ++ks) {
#pragma unroll
            for (int nt = 0; nt < 8; ++nt) {
                unsigned int bb[2];
                bb[0] = __float_as_uint(Ks[(8 * nt + g) * PSTR + 8 * ks + t]);
                bb[1] = __float_as_uint(Ks[(8 * nt + g) * PSTR + 8 * ks + t + 4]);
                mma_tf32(s[nt], qf[ks], bb);
            }
        }

        // Online softmax: row g -> s[nt][0..1], row g+8 -> s[nt][2..3]
        float tm0 = -1e30f, tm1 = -1e30f;
#pragma unroll
        for (int nt = 0; nt < 8; ++nt) {
            tm0 = fmaxf(tm0, fmaxf(s[nt][0], s[nt][1]));
            tm1 = fmaxf(tm1, fmaxf(s[nt][2], s[nt][3]));
        }
        tm0 = fmaxf(tm0, __shfl_xor_sync(0xffffffffu, tm0, 1));
        tm0 = fmaxf(tm0, __shfl_xor_sync(0xffffffffu, tm0, 2));
        tm1 = fmaxf(tm1, __shfl_xor_sync(0xffffffffu, tm1, 1));
        tm1 = fmaxf(tm1, __shfl_xor_sync(0xffffffffu, tm1, 2));
        float mn0 = fmaxf(m0, tm0), mn1 = fmaxf(m1, tm1);
        float c0 = __expf(m0 - mn0), c1 = __expf(m1 - mn1);
        m0 = mn0; m1 = mn1;
        float ls0 = 0.f, ls1 = 0.f;
#pragma unroll
        for (int nt = 0; nt < 8; ++nt) {
            s[nt][0] = __expf(s[nt][0] - mn0); ls0 += s[nt][0];
            s[nt][1] = __expf(s[nt][1] - mn0); ls0 += s[nt][1];
            s[nt][2] = __expf(s[nt][2] - mn1); ls1 += s[nt][2];
            s[nt][3] = __expf(s[nt][3] - mn1); ls1 += s[nt][3];
        }
        ls0 += __shfl_xor_sync(0xffffffffu, ls0, 1);
        ls0 += __shfl_xor_sync(0xffffffffu, ls0, 2);
        ls1 += __shfl_xor_sync(0xffffffffu, ls1, 1);
        ls1 += __shfl_xor_sync(0xffffffffu, ls1, 2);
        l0 = l0 * c0 + ls0;
        l1 = l1 * c1 + ls1;
#pragma unroll
        for (int nt = 0; nt < 8; ++nt) {
            oa[nt][0] *= c0; oa[nt][1] *= c0;
            oa[nt][2] *= c1; oa[nt][3] *= c1;
        }

        // P (tf32) into this warp's own QP rows
#pragma unroll
        for (int nt = 0; nt < 8; ++nt) {
            *(float2*)&QP[(mr)     * PSTR + 8 * nt + 2 * t] =
                make_float2(tf32f(s[nt][0]), tf32f(s[nt][1]));
            *(float2*)&QP[(mr + 8) * PSTR + 8 * nt + 2 * t] =
                make_float2(tf32f(s[nt][2]), tf32f(s[nt][3]));
        }
        __syncwarp();

        // O += P.V : contraction over 64 keys (8 k-steps)
#pragma unroll
        for (int kk = 0; kk < 8; ++kk) {
            unsigned int pf[4];
            pf[0] = __float_as_uint(QP[(mr)     * PSTR + 8 * kk + t]);
            pf[1] = __float_as_uint(QP[(mr + 8) * PSTR + 8 * kk + t]);
            pf[2] = __float_as_uint(QP[(mr)     * PSTR + 8 * kk + t + 4]);
            pf[3] = __float_as_uint(QP[(mr + 8) * PSTR + 8 * kk + t + 4]);
#pragma unroll
            for (int nt = 0; nt < 8; ++nt) {
                unsigned int bb[2];
                bb[0] = __float_as_uint(Vs[(8 * kk + t)     * PSTR + 8 * nt + g]);
                bb[1] = __float_as_uint(Vs[(8 * kk + t + 4) * PSTR + 8 * nt + g]);
                mma_tf32(oa[nt], pf, bb);
            }
        }
    }

    // Epilogue: normalize, write [b, s, h*64 + d]
    const float i0 = 1.f / l0, i1 = 1.f / l1;
#pragma unroll
    for (int nt = 0; nt < 8; ++nt) {
        float* d0 = g_AO + (size_t)(b * S_ + q0 + mr) * D_ + h * HD_ + 8 * nt + 2 * t;
        *(float2*)d0 = make_float2(oa[nt][0] * i0, oa[nt][1] * i0);
        float* d1 = g_AO + (size_t)(b * S_ + q0 + mr + 8) * D_ + h * HD_ + 8 * nt + 2 * t;
        *(float2*)d1 = make_float2(oa[nt][2] * i1, oa[nt][3] * i1);
    }
}

// ---------------------------------------------------------------------------
extern "C" void kernel_launch(void* const* d_in, const int* in_sizes, int n_in,
                              void* d_out, int out_size)
{
    const float* x     = (const float*)d_in[0];
    const float* Wqkv  = (const float*)d_in[1];
    const float* bqkv  = (const float*)d_in[2];
    const float* Wq    = (const float*)d_in[3];
    const float* bq    = (const float*)d_in[4];
    const float* Wproj = (const float*)d_in[5];
    const float* bproj = (const float*)d_in[6];
    float* out = (float*)d_out;

    cudaFuncSetAttribute(attn_kernel,
                         cudaFuncAttributeMaxDynamicSharedMemorySize,
                         ATTN_SMEM_BYTES);

    dim3 blk(256);
    // anchors @ Wqkv : M = B*A = 2048, N = 3072
    gemm_kernel<0><<<dim3(3 * D_ / 128, (B_ * A_) / 128), blk>>>(x, Wqkv, bqkv, nullptr);
    // queries @ Wq : M = B*SQ = 14336, N = 1024
    gemm_kernel<1><<<dim3(D_ / 128, (B_ * SQ_) / 128), blk>>>(x, Wq, bq, nullptr);
    // attention: grid (S/128, H, B) = (64, 16, 2)
    attn_kernel<<<dim3(S_ / 128, H_, B_), blk, ATTN_SMEM_BYTES>>>();
    // g_AO @ Wproj : M = B*S = 16384, N = 1024
    gemm_kernel<2><<<dim3(D_ / 128, (B_ * S_) / 128), blk>>>(x, Wproj, bproj, out);
}

// round 17
// speedup vs baseline: 2.1317x; 1.3005x over previous
#include <cuda_runtime.h>
#include <cstdint>
#include <cstddef>

#define B_  2
#define S_  8192
#define D_  1024
#define H_  16
#define HD_ 64
#define A_  1024
#define SQ_ (S_ - A_)   // 7168

// Scratch (allocation-free rule: __device__ globals)
__device__ float g_Q[(size_t)B_ * H_ * S_ * HD_];   // [b,h,s,d]  64 MB
__device__ float g_K[(size_t)B_ * H_ * A_ * HD_];   // [b,h,a,d]   8 MB
__device__ float g_V[(size_t)B_ * H_ * A_ * HD_];   //             8 MB
__device__ float g_AO[(size_t)B_ * S_ * D_];        // [b,s,h*hd+d] 64 MB

// ---------------------------------------------------------------------------
// TF32 helpers
// ---------------------------------------------------------------------------
__device__ __forceinline__ unsigned int cvt_tf32(float f) {
    unsigned int r;
    asm("cvt.rna.tf32.f32 %0, %1;" : "=r"(r) : "f"(f));
    return r;
}
__device__ __forceinline__ float tf32f(float f) {
    return __uint_as_float(cvt_tf32(f));
}
// split v into hi (tf32) and lo (tf32 of residual)
__device__ __forceinline__ void tf32_split(float v, float& hi, float& lo) {
    unsigned int h = cvt_tf32(v);
    float hf = __uint_as_float(h);
    unsigned int l = cvt_tf32(v - hf);
    hi = hf; lo = __uint_as_float(l);
}

__device__ __forceinline__ void mma_tf32(float c[4], const unsigned int a[4],
                                         const unsigned int b[2]) {
    asm("mma.sync.aligned.m16n8k8.row.col.f32.tf32.tf32.f32 "
        "{%0,%1,%2,%3}, {%4,%5,%6,%7}, {%8,%9}, {%0,%1,%2,%3};"
        : "+f"(c[0]), "+f"(c[1]), "+f"(c[2]), "+f"(c[3])
        : "r"(a[0]), "r"(a[1]), "r"(a[2]), "r"(a[3]), "r"(b[0]), "r"(b[1]));
}

// ---------------------------------------------------------------------------
// 2-term TF32 tensor-core GEMM: A = Ahi + Alo (exact split), B rounded once.
// 128x128 block tile, K-tile 16, 256 threads (8 warps), warp tile 32x64.
// Register prefetch: next global tile loaded before the compute phase so the
// MMA loop hides the load latency.
// MODE 0: anchors @ Wqkv (+bqkv) -> scatter g_Q/g_K/g_V
// MODE 1: queries @ Wq   (+bq)   -> scatter g_Q
// MODE 2: g_AO @ Wproj   (+bproj)-> d_out
// ---------------------------------------------------------------------------
#define ASTR 20
#define BSTR 136

template <int MODE>
__global__ __launch_bounds__(256, 2) void gemm_kernel(
    const float* __restrict__ Ain, const float* __restrict__ Bw,
    const float* __restrict__ bias, float* __restrict__ Cout)
{
    constexpr int NN = (MODE == 0) ? 3 * D_ : D_;

    __shared__ float Ah[128 * ASTR], Al[128 * ASTR];
    __shared__ float Bh[16 * BSTR];

    const int tid = threadIdx.x;
    const int wid = tid >> 5;
    const int lane = tid & 31;
    const int g = lane >> 2;        // groupID
    const int t = lane & 3;         // threadID_in_group
    const int m0w = (wid & 3) * 32;
    const int n0w = (wid >> 2) * 64;
    const int rm0 = blockIdx.y * 128;
    const int cn0 = blockIdx.x * 128;

    const int a_m = tid >> 2;
    const int a_k = (tid & 3) << 2;

    auto arowptr = [&](int m) -> const float* {
        int r = rm0 + m;
        if constexpr (MODE == 0) {
            int b = r >> 10, s = r & (A_ - 1);
            return Ain + (size_t)(b * S_ + s) * D_;
        } else if constexpr (MODE == 1) {
            int b = r / SQ_, s = r - b * SQ_;
            return Ain + (size_t)(b * S_ + A_ + s) * D_;
        } else {
            return g_AO + (size_t)r * D_;
        }
    };
    const float* arow0 = arowptr(a_m);
    const float* arow1 = arowptr(a_m + 64);

    const int b_k = tid >> 5;
    const int b_c = (tid & 31) << 2;
    const float* bptr = Bw + (size_t)b_k * NN + cn0 + b_c;

    float acc[2][8][4];
#pragma unroll
    for (int mt = 0; mt < 2; mt++)
#pragma unroll
        for (int nt = 0; nt < 8; nt++)
#pragma unroll
            for (int e = 0; e < 4; e++) acc[mt][nt][e] = 0.f;

    // Prologue: load tile 0 into registers
    float4 av0 = *(const float4*)(arow0 + a_k);
    float4 av1 = *(const float4*)(arow1 + a_k);
    float4 bv0 = *(const float4*)(bptr);
    float4 bv1 = *(const float4*)(bptr + (size_t)8 * NN);

#pragma unroll 1
    for (int kt = 0; kt < D_ / 16; ++kt) {
        __syncthreads();
        // split + store A
        {
            float4 h4, l4;
            tf32_split(av0.x, h4.x, l4.x); tf32_split(av0.y, h4.y, l4.y);
            tf32_split(av0.z, h4.z, l4.z); tf32_split(av0.w, h4.w, l4.w);
            *(float4*)&Ah[a_m * ASTR + a_k] = h4;
            *(float4*)&Al[a_m * ASTR + a_k] = l4;
            tf32_split(av1.x, h4.x, l4.x); tf32_split(av1.y, h4.y, l4.y);
            tf32_split(av1.z, h4.z, l4.z); tf32_split(av1.w, h4.w, l4.w);
            *(float4*)&Ah[(a_m + 64) * ASTR + a_k] = h4;
            *(float4*)&Al[(a_m + 64) * ASTR + a_k] = l4;
        }
        // round + store B
        {
            float4 h4;
            h4.x = tf32f(bv0.x); h4.y = tf32f(bv0.y);
            h4.z = tf32f(bv0.z); h4.w = tf32f(bv0.w);
            *(float4*)&Bh[b_k * BSTR + b_c] = h4;
            h4.x = tf32f(bv1.x); h4.y = tf32f(bv1.y);
            h4.z = tf32f(bv1.z); h4.w = tf32f(bv1.w);
            *(float4*)&Bh[(b_k + 8) * BSTR + b_c] = h4;
        }
        __syncthreads();

        // Prefetch next tile (clamped; redundant reload of tile 0 on last iter)
        const int kg2 = ((kt + 1 < D_ / 16) ? (kt + 1) : 0) << 4;
        av0 = *(const float4*)(arow0 + kg2 + a_k);
        av1 = *(const float4*)(arow1 + kg2 + a_k);
        bv0 = *(const float4*)(bptr + (size_t)kg2 * NN);
        bv1 = *(const float4*)(bptr + (size_t)(kg2 + 8) * NN);

#pragma unroll
        for (int ks = 0; ks < 16; ks += 8) {
            unsigned int ahi[2][4], alo[2][4];
#pragma unroll
            for (int mt = 0; mt < 2; mt++) {
                int mrow = m0w + mt * 16 + g;
                ahi[mt][0] = __float_as_uint(Ah[(mrow)     * ASTR + ks + t]);
                ahi[mt][1] = __float_as_uint(Ah[(mrow + 8) * ASTR + ks + t]);
                ahi[mt][2] = __float_as_uint(Ah[(mrow)     * ASTR + ks + t + 4]);
                ahi[mt][3] = __float_as_uint(Ah[(mrow + 8) * ASTR + ks + t + 4]);
                alo[mt][0] = __float_as_uint(Al[(mrow)     * ASTR + ks + t]);
                alo[mt][1] = __float_as_uint(Al[(mrow + 8) * ASTR + ks + t]);
                alo[mt][2] = __float_as_uint(Al[(mrow)     * ASTR + ks + t + 4]);
                alo[mt][3] = __float_as_uint(Al[(mrow + 8) * ASTR + ks + t + 4]);
            }
#pragma unroll
            for (int nt = 0; nt < 8; nt++) {
                int ncol = n0w + nt * 8 + g;
                unsigned int bb[2];
                bb[0] = __float_as_uint(Bh[(ks + t)     * BSTR + ncol]);
                bb[1] = __float_as_uint(Bh[(ks + t + 4) * BSTR + ncol]);
#pragma unroll
                for (int mt = 0; mt < 2; mt++) {
                    mma_tf32(acc[mt][nt], ahi[mt], bb);
                    mma_tf32(acc[mt][nt], alo[mt], bb);
                }
            }
        }
    }

#pragma unroll
    for (int nt = 0; nt < 8; nt++) {
        int c = cn0 + n0w + nt * 8 + 2 * t;
        float2 bi = *(const float2*)&bias[c];
#pragma unroll
        for (int mt = 0; mt < 2; mt++) {
#pragma unroll
            for (int half = 0; half < 2; half++) {
                int r = rm0 + m0w + mt * 16 + g + half * 8;
                float2 v = make_float2(acc[mt][nt][2 * half] + bi.x,
                                       acc[mt][nt][2 * half + 1] + bi.y);
                float* dst;
                if constexpr (MODE == 0) {
                    int b = r >> 10, s = r & (A_ - 1);
                    int three = c >> 10;
                    int rem = c & 1023;
                    int h = rem >> 6, d = rem & 63;
                    if (three == 0)
                        dst = g_Q + ((size_t)(b * H_ + h) * S_ + s) * HD_ + d;
                    else if (three == 1)
                        dst = g_K + ((size_t)(b * H_ + h) * A_ + s) * HD_ + d;
                    else
                        dst = g_V + ((size_t)(b * H_ + h) * A_ + s) * HD_ + d;
                } else if constexpr (MODE == 1) {
                    int b = r / SQ_, s = r - b * SQ_;
                    int h = c >> 6, d = c & 63;
                    dst = g_Q + ((size_t)(b * H_ + h) * S_ + (A_ + s)) * HD_ + d;
                } else {
                    dst = Cout + (size_t)r * D_ + c;
                }
                *(float2*)dst = v;
            }
        }
    }
}

// ---------------------------------------------------------------------------
// Flash attention: 1x TF32 MMA with latency-hiding staging.
// Per key-tile: K is stored from prefetched regs (prefetched during the
// previous tile's PV phase); V's global loads are issued before the S phase
// and stored after it. All load latencies overlap MMA work.
// 128 queries/block, 256 threads (8 warps); warp owns 16 q-rows x all keys.
// ---------------------------------------------------------------------------
#define PSTR 72
#define ATTN_SMEM_FLOATS (128 * PSTR + 64 * PSTR + 64 * PSTR)   // 18432
#define ATTN_SMEM_BYTES  (ATTN_SMEM_FLOATS * 4)                 // 72 KB

__global__ __launch_bounds__(256, 2) void attn_kernel()
{
    extern __shared__ float sm[];
    float* QP = sm;                       // [128][72]  Q staging, then P
    float* Ks = QP + 128 * PSTR;          // [64][72]   K tile [key][d]
    float* Vs = Ks + 64 * PSTR;           // [64][72]   V tile [key][d]

    const int tid = threadIdx.x;
    const int wid = tid >> 5;
    const int lane = tid & 31;
    const int g = lane >> 2;
    const int t = lane & 3;
    const int b = blockIdx.z, h = blockIdx.y;
    const int bh = b * H_ + h;
    const int q0 = blockIdx.x * 128;

    const float* Qg = g_Q + ((size_t)bh * S_ + q0) * HD_;
    const float* Kb = g_K + (size_t)bh * A_ * HD_;
    const float* Vb = g_V + (size_t)bh * A_ * HD_;

    // Per-thread K/V tile mapping (4 float4s each)
    int krow[4], kcol[4];
#pragma unroll
    for (int j = 0; j < 4; ++j) {
        int idx = j * 256 + tid;          // 0..1023 float4s
        krow[j] = idx >> 4;               // key 0..63
        kcol[j] = (idx & 15) << 2;        // d offset
    }

    // Stage Q tile: scale by 1/sqrt(hd), convert to tf32
#pragma unroll
    for (int j = 0; j < 8; ++j) {
        int idx = j * 256 + tid;
        int row = idx >> 4;
        int dg  = idx & 15;
        float4 v = ((const float4*)(Qg + (size_t)row * HD_))[dg];
        float* p = &QP[row * PSTR + 4 * dg];
        p[0] = tf32f(v.x * 0.125f);
        p[1] = tf32f(v.y * 0.125f);
        p[2] = tf32f(v.z * 0.125f);
        p[3] = tf32f(v.w * 0.125f);
    }
    __syncthreads();

    const int mr = wid * 16 + g;
    unsigned int qf[8][4];
#pragma unroll
    for (int ks = 0; ks < 8; ++ks) {
        qf[ks][0] = __float_as_uint(QP[(mr)     * PSTR + 8 * ks + t]);
        qf[ks][1] = __float_as_uint(QP[(mr + 8) * PSTR + 8 * ks + t]);
        qf[ks][2] = __float_as_uint(QP[(mr)     * PSTR + 8 * ks + t + 4]);
        qf[ks][3] = __float_as_uint(QP[(mr + 8) * PSTR + 8 * ks + t + 4]);
    }

    float oa[8][4];
#pragma unroll
    for (int nt = 0; nt < 8; nt++)
#pragma unroll
        for (int e = 0; e < 4; e++) oa[nt][e] = 0.f;
    float m0 = -1e30f, m1 = -1e30f, l0 = 0.f, l1 = 0.f;

    // Prologue: prefetch K tile 0
    float4 kpre[4];
#pragma unroll
    for (int j = 0; j < 4; ++j)
        kpre[j] = *(const float4*)(Kb + (size_t)krow[j] * HD_ + kcol[j]);

#pragma unroll 1
    for (int kt = 0; kt < A_ / 64; ++kt) {
        const float* Vt = Vb + (size_t)kt * 64 * HD_;

        __syncthreads();   // all warps done with prev tile's Ks/Vs
        // Store K (from prefetch) and issue V loads (consumed after S phase)
        float4 vpre[4];
#pragma unroll
        for (int j = 0; j < 4; ++j) {
            float* kp = &Ks[krow[j] * PSTR + kcol[j]];
            kp[0] = tf32f(kpre[j].x); kp[1] = tf32f(kpre[j].y);
            kp[2] = tf32f(kpre[j].z); kp[3] = tf32f(kpre[j].w);
            vpre[j] = *(const float4*)(Vt + (size_t)krow[j] * HD_ + kcol[j]);
        }
        __syncthreads();   // K visible

        // S = Q.K^T : m16 x n64 per warp
        float s[8][4];
#pragma unroll
        for (int nt = 0; nt < 8; nt++)
#pragma unroll
            for (int e = 0; e < 4; e++) s[nt][e] = 0.f;

#pragma unroll
        for (int ks = 0; ks < 8; ++ks) {
#pragma unroll
            for (int nt = 0; nt < 8; ++nt) {
                unsigned int bb[2];
                bb[0] = __float_as_uint(Ks[(8 * nt + g) * PSTR + 8 * ks + t]);
                bb[1] = __float_as_uint(Ks[(8 * nt + g) * PSTR + 8 * ks + t + 4]);
                mma_tf32(s[nt], qf[ks], bb);
            }
        }

        // Online softmax
        float tm0 = -1e30f, tm1 = -1e30f;
#pragma unroll
        for (int nt = 0; nt < 8; ++nt) {
            tm0 = fmaxf(tm0, fmaxf(s[nt][0], s[nt][1]));
            tm1 = fmaxf(tm1, fmaxf(s[nt][2], s[nt][3]));
        }
        tm0 = fmaxf(tm0, __shfl_xor_sync(0xffffffffu, tm0, 1));
        tm0 = fmaxf(tm0, __shfl_xor_sync(0xffffffffu, tm0, 2));
        tm1 = fmaxf(tm1, __shfl_xor_sync(0xffffffffu, tm1, 1));
        tm1 = fmaxf(tm1, __shfl_xor_sync(0xffffffffu, tm1, 2));
        float mn0 = fmaxf(m0, tm0), mn1 = fmaxf(m1, tm1);
        float c0 = __expf(m0 - mn0), c1 = __expf(m1 - mn1);
        m0 = mn0; m1 = mn1;
        float ls0 = 0.f, ls1 = 0.f;
#pragma unroll
        for (int nt = 0; nt < 8; ++nt) {
            s[nt][0] = __expf(s[nt][0] - mn0); ls0 += s[nt][0];
            s[nt][1] = __expf(s[nt][1] - mn0); ls0 += s[nt][1];
            s[nt][2] = __expf(s[nt][2] - mn1); ls1 += s[nt][2];
            s[nt][3] = __expf(s[nt][3] - mn1); ls1 += s[nt][3];
        }
        ls0 += __shfl_xor_sync(0xffffffffu, ls0, 1);
        ls0 += __shfl_xor_sync(0xffffffffu, ls0, 2);
        ls1 += __shfl_xor_sync(0xffffffffu, ls1, 1);
        ls1 += __shfl_xor_sync(0xffffffffu, ls1, 2);
        l0 = l0 * c0 + ls0;
        l1 = l1 * c1 + ls1;
#pragma unroll
        for (int nt = 0; nt < 8; ++nt) {
            oa[nt][0] *= c0; oa[nt][1] *= c0;
            oa[nt][2] *= c1; oa[nt][3] *= c1;
        }

        // P (tf32) into this warp's own QP rows
#pragma unroll
        for (int nt = 0; nt < 8; ++nt) {
            *(float2*)&QP[(mr)     * PSTR + 8 * nt + 2 * t] =
                make_float2(tf32f(s[nt][0]), tf32f(s[nt][1]));
            *(float2*)&QP[(mr + 8) * PSTR + 8 * nt + 2 * t] =
                make_float2(tf32f(s[nt][2]), tf32f(s[nt][3]));
        }
        __syncwarp();

        // Store V (loads issued before S phase -> latency hidden),
        // prefetch next K (consumed after next sync -> hidden by PV)
        {
            const float* Kn = Kb + (size_t)((kt + 1 < A_ / 64) ? kt + 1 : 0) * 64 * HD_;
#pragma unroll
            for (int j = 0; j < 4; ++j) {
                float* vp = &Vs[krow[j] * PSTR + kcol[j]];
                vp[0] = tf32f(vpre[j].x); vp[1] = tf32f(vpre[j].y);
                vp[2] = tf32f(vpre[j].z); vp[3] = tf32f(vpre[j].w);
                kpre[j] = *(const float4*)(Kn + (size_t)krow[j] * HD_ + kcol[j]);
            }
        }
        __syncthreads();   // V visible

        // O += P.V
#pragma unroll
        for (int kk = 0; kk < 8; ++kk) {
            unsigned int pf[4];
            pf[0] = __float_as_uint(QP[(mr)     * PSTR + 8 * kk + t]);
            pf[1] = __float_as_uint(QP[(mr + 8) * PSTR + 8 * kk + t]);
            pf[2] = __float_as_uint(QP[(mr)     * PSTR + 8 * kk + t + 4]);
            pf[3] = __float_as_uint(QP[(mr + 8) * PSTR + 8 * kk + t + 4]);
#pragma unroll
            for (int nt = 0; nt < 8; ++nt) {
                unsigned int bb[2];
                bb[0] = __float_as_uint(Vs[(8 * kk + t)     * PSTR + 8 * nt + g]);
                bb[1] = __float_as_uint(Vs[(8 * kk + t + 4) * PSTR + 8 * nt + g]);
                mma_tf32(oa[nt], pf, bb);
            }
        }
    }

    // Epilogue: normalize, write [b, s, h*64 + d]
    const float i0 = 1.f / l0, i1 = 1.f / l1;
#pragma unroll
    for (int nt = 0; nt < 8; ++nt) {
        float* d0 = g_AO + (size_t)(b * S_ + q0 + mr) * D_ + h * HD_ + 8 * nt + 2 * t;
        *(float2*)d0 = make_float2(oa[nt][0] * i0, oa[nt][1] * i0);
        float* d1 = g_AO + (size_t)(b * S_ + q0 + mr + 8) * D_ + h * HD_ + 8 * nt + 2 * t;
        *(float2*)d1 = make_float2(oa[nt][2] * i1, oa[nt][3] * i1);
    }
}

// ---------------------------------------------------------------------------
extern "C" void kernel_launch(void* const* d_in, const int* in_sizes, int n_in,
                              void* d_out, int out_size)
{
    const float* x     = (const float*)d_in[0];
    const float* Wqkv  = (const float*)d_in[1];
    const float* bqkv  = (const float*)d_in[2];
    const float* Wq    = (const float*)d_in[3];
    const float* bq    = (const float*)d_in[4];
    const float* Wproj = (const float*)d_in[5];
    const float* bproj = (const float*)d_in[6];
    float* out = (float*)d_out;

    cudaFuncSetAttribute(attn_kernel,
                         cudaFuncAttributeMaxDynamicSharedMemorySize,
                         ATTN_SMEM_BYTES);

    dim3 blk(256);
    // anchors @ Wqkv : M = B*A = 2048, N = 3072
    gemm_kernel<0><<<dim3(3 * D_ / 128, (B_ * A_) / 128), blk>>>(x, Wqkv, bqkv, nullptr);
    // queries @ Wq : M = B*SQ = 14336, N = 1024
    gemm_kernel<1><<<dim3(D_ / 128, (B_ * SQ_) / 128), blk>>>(x, Wq, bq, nullptr);
    // attention: grid (S/128, H, B) = (64, 16, 2)
    attn_kernel<<<dim3(S_ / 128, H_, B_), blk, ATTN_SMEM_BYTES>>>();
    // g_AO @ Wproj : M = B*S = 16384, N = 1024
    gemm_kernel<2><<<dim3(D_ / 128, (B_ * S_) / 128), blk>>>(x, Wproj, bproj, out);
}